// round 8
// baseline (speedup 1.0000x reference)
#include <cuda_runtime.h>

#define N_NODES 200000
#define N_EDGES 3200000
#define SCAN_BLOCKS 196   // ceil(200000 / 1024); co-resident (196 < 148*8)
#define BUILD_THREADS (SCAN_BLOCKS * 256)

// ---------------- scratch (device globals; zero-initialized at module load) ----------------
__device__ __align__(16) int    g_deg[N_NODES];      // invariant: zero at kernel_launch entry
__device__ __align__(16) int    g_off[N_NODES + 1];
__device__ __align__(16) int    g_cursor[N_NODES];
__device__ __align__(16) int    g_flag[256];         // invariant: zero at kernel_launch entry
__device__ volatile int         g_barcnt;            // invariant: zero at entry (reset by k_scatter)
__device__ __align__(16) int    g_src[N_EDGES];
__device__ __align__(16) float2 g_kw[N_EDGES];
__device__ __align__(16) float  g_h32[N_NODES * 32];
__device__ __align__(16) float  g_h64[N_NODES * 64];
__device__ __align__(16) float2 g_hid[64 * N_NODES];  // hidden, transposed: [pair][node]

typedef unsigned long long ull;

__device__ __forceinline__ ull fma2(ull a, ull b, ull c) {
    ull d;
    asm("fma.rn.f32x2 %0, %1, %2, %3;" : "=l"(d) : "l"(a), "l"(b), "l"(c));
    return d;
}
__device__ __forceinline__ ull pack2(float x, float y) {
    ull r;
    asm("mov.b64 %0, {%1, %2};" : "=l"(r) : "f"(x), "f"(y));
    return r;
}
__device__ __forceinline__ float2 unpack2(ull v) {
    float2 r;
    asm("mov.b64 {%0, %1}, %2;" : "=f"(r.x), "=f"(r.y) : "l"(v));
    return r;
}

// ---------------- fused hist + scan (persistent, one grid barrier) ----------------
__global__ void __launch_bounds__(256) k_histscan(const int* __restrict__ ei) {
    int t = threadIdx.x;
    int b = blockIdx.x;
    int gtid = b * 256 + t;

    // phase 1: degree histogram (grid-stride, coalesced reads, fire-and-forget atomics)
    for (int e = gtid; e < N_EDGES; e += BUILD_THREADS)
        atomicAdd(&g_deg[ei[N_EDGES + e]], 1);

    // grid barrier (monotonic counter; reset to 0 by k_scatter for next replay)
    __syncthreads();
    if (t == 0) {
        __threadfence();
        atomicAdd((int*)&g_barcnt, 1);
        while (g_barcnt < SCAN_BLOCKS) { }
        __threadfence();
    }
    __syncthreads();

    // phase 2: block-local scan + spin-flag lookback
    __shared__ int sh[256];
    __shared__ int red[8];
    int base = b * 1024 + t * 4;
    int v0 = 0, v1 = 0, v2 = 0, v3 = 0;
    if (base + 0 < N_NODES) v0 = g_deg[base + 0];
    if (base + 1 < N_NODES) v1 = g_deg[base + 1];
    if (base + 2 < N_NODES) v2 = g_deg[base + 2];
    if (base + 3 < N_NODES) v3 = g_deg[base + 3];
    int tot = v0 + v1 + v2 + v3;
    sh[t] = tot;
    __syncthreads();
    for (int d = 1; d < 256; d <<= 1) {
        int xv = (t >= d) ? sh[t - d] : 0;
        __syncthreads();
        sh[t] += xv;
        __syncthreads();
    }
    if (t == 255) ((volatile int*)g_flag)[b] = sh[255] + 1;  // publish block total

    int v = 0;
    if (t < b) {
        volatile int* f = (volatile int*)g_flag;
        int fv;
        while ((fv = f[t]) == 0) {}
        v = fv - 1;
    }
#pragma unroll
    for (int d = 16; d > 0; d >>= 1) v += __shfl_down_sync(0xffffffffu, v, d);
    if ((t & 31) == 0) red[t >> 5] = v;
    __syncthreads();
    int prefix = red[0] + red[1] + red[2] + red[3] + red[4] + red[5] + red[6] + red[7];

    int excl = sh[t] - tot + prefix;
    int e0 = excl, e1 = excl + v0, e2 = excl + v0 + v1, e3 = excl + v0 + v1 + v2;
    if (base + 0 < N_NODES) { g_off[base + 0] = e0; g_cursor[base + 0] = e0; g_deg[base + 0] = 0; }
    if (base + 1 < N_NODES) { g_off[base + 1] = e1; g_cursor[base + 1] = e1; g_deg[base + 1] = 0; }
    if (base + 2 < N_NODES) { g_off[base + 2] = e2; g_cursor[base + 2] = e2; g_deg[base + 2] = 0; }
    if (base + 3 < N_NODES) { g_off[base + 3] = e3; g_cursor[base + 3] = e3; g_deg[base + 3] = 0; }
    if (b == 0 && t == 0) g_off[N_NODES] = N_EDGES;
}

__global__ void k_scatter(const int* __restrict__ ei, const float* __restrict__ Kw) {
    int e = blockIdx.x * blockDim.x + threadIdx.x;
    if (e < 256) g_flag[e] = 0;     // restore scan-flag invariant for next replay
    if (e == 0) g_barcnt = 0;       // restore grid-barrier invariant for next replay
    if (e >= N_EDGES) return;
    int s = ei[e];
    int d = ei[N_EDGES + e];
    float k0 = Kw[e];
    float k1 = Kw[N_EDGES + e];
    int p = atomicAdd(&g_cursor[d], 1);
    g_src[p] = s;
    g_kw[p] = make_float2(k0, k1);
}

// ---------------- layer 0: conv (d=8, nk=2) fused with MLP 16->32 + L2 norm ----------------
// warp per node: conv lanes = 8 features x 4 edge-subsets; shuffle-broadcast h16;
// each lane computes one of 32 MLP outputs; warp-reduce norm; coalesced 128B store.
__global__ void k_conv0mlp0(const float* __restrict__ x,
                            const float* __restrict__ W0, const float* __restrict__ b0) {
    __shared__ float W0s[512];
    __shared__ float b0s[32];
    for (int i = threadIdx.x; i < 512; i += blockDim.x) W0s[i] = W0[i];
    if (threadIdx.x < 32) b0s[threadIdx.x] = b0[threadIdx.x];
    __syncthreads();

    int warp = threadIdx.x >> 5, lane = threadIdx.x & 31;
    int node = blockIdx.x * 8 + warp;
    if (node >= N_NODES) return;
    int f = lane & 7, sub = lane >> 3;
    int beg = g_off[node], end = g_off[node + 1];
    float a0 = 0.f, a1 = 0.f;
    for (int k = beg + sub; k < end; k += 4) {
        int s = g_src[k];
        float2 kw = g_kw[k];
        float xv = x[s * 8 + f];
        a0 = fmaf(kw.x, xv, a0);
        a1 = fmaf(kw.y, xv, a1);
    }
    a0 += __shfl_xor_sync(0xffffffffu, a0, 8);
    a0 += __shfl_xor_sync(0xffffffffu, a0, 16);
    a1 += __shfl_xor_sync(0xffffffffu, a1, 8);
    a1 += __shfl_xor_sync(0xffffffffu, a1, 16);

    // broadcast h16: h[i] = (i<8 ? a0 : a1) from lane (i&7)
    float h[16];
#pragma unroll
    for (int i = 0; i < 16; i++) {
        float hv = (i < 8) ? a0 : a1;
        h[i] = __shfl_sync(0xffffffffu, hv, i & 7);
    }
    float acc = b0s[lane];
#pragma unroll
    for (int i = 0; i < 16; i++) acc = fmaf(h[i], W0s[i * 32 + lane], acc);
    float ss = acc * acc;
#pragma unroll
    for (int d = 16; d > 0; d >>= 1) ss += __shfl_xor_sync(0xffffffffu, ss, d);
    float inv = 1.f / fmaxf(sqrtf(ss), 1e-12f);
    g_h32[node * 32 + lane] = acc * inv;
}

// ---------------- layer 1: conv (d=32, nk=2) ----------------
// warp per node; wide broadcast edge loads (int4 src + 2x float4 kw per 4 edges)
__global__ void k_conv1() {
    int warp = threadIdx.x >> 5, lane = threadIdx.x & 31;
    int node = blockIdx.x * 8 + warp;
    if (node >= N_NODES) return;
    int beg = g_off[node], end = g_off[node + 1];
    float a0 = 0.f, a1 = 0.f;

    int k = beg;
    int pre = (beg + 3) & ~3;               // align k to 4 (16B for src, 16B for kw pairs)
    if (pre > end) pre = end;
    for (; k < pre; k++) {
        int s = g_src[k];
        float2 w = g_kw[k];
        float v = g_h32[s * 32 + lane];
        a0 = fmaf(w.x, v, a0);
        a1 = fmaf(w.y, v, a1);
    }
    for (; k + 4 <= end; k += 4) {
        int4 s4 = *(const int4*)&g_src[k];            // 1 broadcast LDG.128 = 4 srcs
        float4 ka = *(const float4*)&g_kw[k];         // kw[k], kw[k+1]
        float4 kb = *(const float4*)&g_kw[k + 2];     // kw[k+2], kw[k+3]
        float v0 = g_h32[s4.x * 32 + lane];
        float v1 = g_h32[s4.y * 32 + lane];
        float v2 = g_h32[s4.z * 32 + lane];
        float v3 = g_h32[s4.w * 32 + lane];
        a0 = fmaf(ka.x, v0, a0); a1 = fmaf(ka.y, v0, a1);
        a0 = fmaf(ka.z, v1, a0); a1 = fmaf(ka.w, v1, a1);
        a0 = fmaf(kb.x, v2, a0); a1 = fmaf(kb.y, v2, a1);
        a0 = fmaf(kb.z, v3, a0); a1 = fmaf(kb.w, v3, a1);
    }
    for (; k < end; k++) {
        int s = g_src[k];
        float2 w = g_kw[k];
        float v = g_h32[s * 32 + lane];
        a0 = fmaf(w.x, v, a0);
        a1 = fmaf(w.y, v, a1);
    }
    g_h64[node * 64 + lane]      = a0;
    g_h64[node * 64 + 32 + lane] = a1;
}

// ---------------- layer 1 MLP pass A: 64 -> 128, ReLU (unchanged from R7) ----------------
__global__ void __launch_bounds__(256) k_mlp1a(
    const float* __restrict__ W1, const float* __restrict__ b1)
{
    __shared__ float W1s[64 * 128];
    __shared__ float b1s[128];
    for (int idx = threadIdx.x; idx < 8192; idx += 256) W1s[idx] = W1[idx];
    if (threadIdx.x < 128) b1s[threadIdx.x] = b1[threadIdx.x];
    __syncthreads();

    int node = blockIdx.x * 256 + threadIdx.x;
    if (node >= N_NODES) return;

    float h[64];
    const float4* hp = (const float4*)&g_h64[node * 64];
#pragma unroll
    for (int j = 0; j < 16; j++) {
        float4 v = hp[j];
        h[4 * j] = v.x; h[4 * j + 1] = v.y; h[4 * j + 2] = v.z; h[4 * j + 3] = v.w;
    }

#pragma unroll 1
    for (int g = 0; g < 8; g++) {          // 8 groups x 16 outputs
        int ob = g * 16;
        ull acc[8];
#pragma unroll
        for (int j = 0; j < 8; j++) acc[j] = pack2(b1s[ob + 2 * j], b1s[ob + 2 * j + 1]);
#pragma unroll
        for (int i = 0; i < 64; i++) {
            ull hh = pack2(h[i], h[i]);
            const ulonglong2* wr = (const ulonglong2*)&W1s[i * 128 + ob];
            ulonglong2 wa = wr[0], wb = wr[1], wc = wr[2], wd = wr[3];
            acc[0] = fma2(hh, wa.x, acc[0]); acc[1] = fma2(hh, wa.y, acc[1]);
            acc[2] = fma2(hh, wb.x, acc[2]); acc[3] = fma2(hh, wb.y, acc[3]);
            acc[4] = fma2(hh, wc.x, acc[4]); acc[5] = fma2(hh, wc.y, acc[5]);
            acc[6] = fma2(hh, wd.x, acc[6]); acc[7] = fma2(hh, wd.y, acc[7]);
        }
#pragma unroll
        for (int j = 0; j < 8; j++) {
            float2 v = unpack2(acc[j]);
            g_hid[(g * 8 + j) * N_NODES + node] =
                make_float2(fmaxf(v.x, 0.f), fmaxf(v.y, 0.f));
        }
    }
}

// ---------------- layer 1 MLP pass B: 128 -> 64 + L2 norm (unchanged from R7) ----------------
__global__ void __launch_bounds__(256) k_mlp1b(
    const float* __restrict__ W2, const float* __restrict__ b2,
    float* __restrict__ out)
{
    __shared__ float W2s[128 * 64];
    __shared__ float b2s[64];
    for (int idx = threadIdx.x; idx < 8192; idx += 256) W2s[idx] = W2[idx];
    if (threadIdx.x < 64) b2s[threadIdx.x] = b2[threadIdx.x];
    __syncthreads();

    int node = blockIdx.x * 256 + threadIdx.x;
    if (node >= N_NODES) return;

    ull out2[32];
#pragma unroll
    for (int m = 0; m < 32; m++) out2[m] = pack2(b2s[2 * m], b2s[2 * m + 1]);

#pragma unroll 1
    for (int c = 0; c < 8; c++) {          // 8 chunks x 8 hidden-pairs (16 rows)
        float2 hp[8];
#pragma unroll
        for (int q = 0; q < 8; q++) hp[q] = g_hid[(c * 8 + q) * N_NODES + node];
#pragma unroll
        for (int q = 0; q < 8; q++) {
            int r0 = (c * 8 + q) * 2;
            ull hh0 = pack2(hp[q].x, hp[q].x);
            const ulonglong2* w0 = (const ulonglong2*)&W2s[r0 * 64];
#pragma unroll
            for (int j = 0; j < 16; j++) {
                ulonglong2 w = w0[j];
                out2[2 * j]     = fma2(hh0, w.x, out2[2 * j]);
                out2[2 * j + 1] = fma2(hh0, w.y, out2[2 * j + 1]);
            }
            ull hh1 = pack2(hp[q].y, hp[q].y);
            const ulonglong2* w1 = (const ulonglong2*)&W2s[(r0 + 1) * 64];
#pragma unroll
            for (int j = 0; j < 16; j++) {
                ulonglong2 w = w1[j];
                out2[2 * j]     = fma2(hh1, w.x, out2[2 * j]);
                out2[2 * j + 1] = fma2(hh1, w.y, out2[2 * j + 1]);
            }
        }
    }

    float ss = 0.f;
#pragma unroll
    for (int m = 0; m < 32; m++) {
        float2 v = unpack2(out2[m]);
        ss += v.x * v.x + v.y * v.y;
    }
    float inv = 1.f / fmaxf(sqrtf(ss), 1e-12f);
    float2* op = (float2*)&out[node * 64];
#pragma unroll
    for (int m = 0; m < 32; m++) {
        float2 v = unpack2(out2[m]);
        op[m] = make_float2(v.x * inv, v.y * inv);
    }
}

// ---------------- launch ----------------
extern "C" void kernel_launch(void* const* d_in, const int* in_sizes, int n_in,
                              void* d_out, int out_size) {
    const float* x  = (const float*)d_in[0];
    const int*   ei = (const int*)d_in[1];
    const float* Kw = (const float*)d_in[2];
    const float* W0 = (const float*)d_in[3];
    const float* b0 = (const float*)d_in[4];
    const float* W1 = (const float*)d_in[5];
    const float* b1 = (const float*)d_in[6];
    const float* W2 = (const float*)d_in[7];
    const float* b2 = (const float*)d_in[8];
    float* out = (float*)d_out;

    k_histscan<<<SCAN_BLOCKS, 256>>>(ei);       // 1
    k_scatter<<<12500, 256>>>(ei, Kw);          // 2
    k_conv0mlp0<<<25000, 256>>>(x, W0, b0);     // 3
    k_conv1<<<25000, 256>>>();                  // 4  <- ncu capture slot (verify wavefront fix)
    k_mlp1a<<<782, 256>>>(W1, b1);              // 5
    k_mlp1b<<<782, 256>>>(W2, b2, out);         // 6
}

// round 9
// speedup vs baseline: 1.0079x; 1.0079x over previous
#include <cuda_runtime.h>

#define N_NODES 200000
#define N_EDGES 3200000
#define SCAN_BLOCKS 196   // ceil(200000 / 1024)

// ---------------- scratch (device globals; zero-initialized at module load) ----------------
__device__ __align__(16) int    g_deg[N_NODES];      // invariant: zero at kernel_launch entry
__device__ __align__(16) int    g_off[N_NODES + 1];
__device__ __align__(16) int    g_cursor[N_NODES];
__device__ __align__(16) int    g_flag[256];         // invariant: zero at kernel_launch entry
__device__ __align__(16) int    g_src[N_EDGES];
__device__ __align__(16) float2 g_kw[N_EDGES];
__device__ __align__(16) float  g_h16[N_NODES * 16];
__device__ __align__(16) float  g_h32[N_NODES * 32];
__device__ __align__(16) float  g_h64[N_NODES * 64];
__device__ __align__(16) float2 g_hid[64 * N_NODES];  // hidden, transposed: [pair][node]

// ---------------- CSR build ----------------
__global__ void k_hist(const int* __restrict__ ei) {
    int e = blockIdx.x * blockDim.x + threadIdx.x;
    if (e < N_EDGES) atomicAdd(&g_deg[ei[N_EDGES + e]], 1);
}

// single-pass scan: block-local scan + spin-flag lookback over earlier blocks.
__global__ void k_scan() {
    __shared__ int sh[256];
    __shared__ int red[8];
    int t = threadIdx.x;
    int b = blockIdx.x;
    int base = b * 1024 + t * 4;
    int v0 = 0, v1 = 0, v2 = 0, v3 = 0;
    if (base + 0 < N_NODES) v0 = g_deg[base + 0];
    if (base + 1 < N_NODES) v1 = g_deg[base + 1];
    if (base + 2 < N_NODES) v2 = g_deg[base + 2];
    if (base + 3 < N_NODES) v3 = g_deg[base + 3];
    int tot = v0 + v1 + v2 + v3;
    sh[t] = tot;
    __syncthreads();
    for (int d = 1; d < 256; d <<= 1) {
        int xv = (t >= d) ? sh[t - d] : 0;
        __syncthreads();
        sh[t] += xv;
        __syncthreads();
    }
    if (t == 255) ((volatile int*)g_flag)[b] = sh[255] + 1;  // publish block total

    int v = 0;
    if (t < b) {
        volatile int* f = (volatile int*)g_flag;
        int fv;
        while ((fv = f[t]) == 0) {}
        v = fv - 1;
    }
#pragma unroll
    for (int d = 16; d > 0; d >>= 1) v += __shfl_down_sync(0xffffffffu, v, d);
    if ((t & 31) == 0) red[t >> 5] = v;
    __syncthreads();
    int prefix = red[0] + red[1] + red[2] + red[3] + red[4] + red[5] + red[6] + red[7];

    int excl = sh[t] - tot + prefix;
    int e0 = excl, e1 = excl + v0, e2 = excl + v0 + v1, e3 = excl + v0 + v1 + v2;
    if (base + 0 < N_NODES) { g_off[base + 0] = e0; g_cursor[base + 0] = e0; g_deg[base + 0] = 0; }
    if (base + 1 < N_NODES) { g_off[base + 1] = e1; g_cursor[base + 1] = e1; g_deg[base + 1] = 0; }
    if (base + 2 < N_NODES) { g_off[base + 2] = e2; g_cursor[base + 2] = e2; g_deg[base + 2] = 0; }
    if (base + 3 < N_NODES) { g_off[base + 3] = e3; g_cursor[base + 3] = e3; g_deg[base + 3] = 0; }
    if (b == 0 && t == 0) g_off[N_NODES] = N_EDGES;
}

__global__ void k_scatter(const int* __restrict__ ei, const float* __restrict__ Kw) {
    int e = blockIdx.x * blockDim.x + threadIdx.x;
    if (e < 256) g_flag[e] = 0;   // restore scan-flag invariant for next replay
    if (e >= N_EDGES) return;
    int s = ei[e];
    int d = ei[N_EDGES + e];
    float k0 = Kw[e];
    float k1 = Kw[N_EDGES + e];
    int p = atomicAdd(&g_cursor[d], 1);
    g_src[p] = s;
    g_kw[p] = make_float2(k0, k1);
}

// ---------------- layer 0: conv (d=8, nk=2) ----------------
__global__ void k_conv0(const float* __restrict__ x) {
    int warp = threadIdx.x >> 5, lane = threadIdx.x & 31;
    int node = blockIdx.x * 8 + warp;
    if (node >= N_NODES) return;
    int f = lane & 7, sub = lane >> 3;
    int beg = g_off[node], end = g_off[node + 1];
    float a0 = 0.f, a1 = 0.f;
    for (int k = beg + sub; k < end; k += 4) {
        int s = g_src[k];
        float2 kw = g_kw[k];
        float xv = x[s * 8 + f];
        a0 = fmaf(kw.x, xv, a0);
        a1 = fmaf(kw.y, xv, a1);
    }
    a0 += __shfl_xor_sync(0xffffffffu, a0, 8);
    a0 += __shfl_xor_sync(0xffffffffu, a0, 16);
    a1 += __shfl_xor_sync(0xffffffffu, a1, 8);
    a1 += __shfl_xor_sync(0xffffffffu, a1, 16);
    if (sub == 0) {
        g_h16[node * 16 + f]     = a0;
        g_h16[node * 16 + 8 + f] = a1;
    }
}

// ---------------- layer 0: MLP 16->32 + L2 norm ----------------
__global__ void k_mlp0(const float* __restrict__ W0, const float* __restrict__ b0) {
    __shared__ float W0s[512];
    __shared__ float b0s[32];
    for (int i = threadIdx.x; i < 512; i += blockDim.x) W0s[i] = W0[i];
    if (threadIdx.x < 32) b0s[threadIdx.x] = b0[threadIdx.x];
    __syncthreads();
    int node = blockIdx.x * blockDim.x + threadIdx.x;
    if (node >= N_NODES) return;
    float h[16];
    const float4* hp = (const float4*)&g_h16[node * 16];
#pragma unroll
    for (int j = 0; j < 4; j++) {
        float4 v = hp[j];
        h[4 * j] = v.x; h[4 * j + 1] = v.y; h[4 * j + 2] = v.z; h[4 * j + 3] = v.w;
    }
    float o[32];
    float ss = 0.f;
#pragma unroll
    for (int j = 0; j < 32; j++) {
        float acc = b0s[j];
#pragma unroll
        for (int i = 0; i < 16; i++) acc = fmaf(h[i], W0s[i * 32 + j], acc);
        o[j] = acc;
        ss += acc * acc;
    }
    float inv = 1.f / fmaxf(sqrtf(ss), 1e-12f);
    float4* op = (float4*)&g_h32[node * 32];
#pragma unroll
    for (int j = 0; j < 8; j++)
        op[j] = make_float4(o[4 * j] * inv, o[4 * j + 1] * inv, o[4 * j + 2] * inv, o[4 * j + 3] * inv);
}

// ---------------- layer 1: conv (d=32, nk=2) ----------------
__global__ void k_conv1() {
    int warp = threadIdx.x >> 5, lane = threadIdx.x & 31;
    int node = blockIdx.x * 8 + warp;
    if (node >= N_NODES) return;
    int beg = g_off[node], end = g_off[node + 1];
    float a0 = 0.f, a1 = 0.f;
    int k = beg;
    for (; k + 4 <= end; k += 4) {
        int s0 = g_src[k], s1 = g_src[k + 1], s2 = g_src[k + 2], s3 = g_src[k + 3];
        float2 w0 = g_kw[k], w1 = g_kw[k + 1], w2 = g_kw[k + 2], w3 = g_kw[k + 3];
        float v0 = g_h32[s0 * 32 + lane];
        float v1 = g_h32[s1 * 32 + lane];
        float v2 = g_h32[s2 * 32 + lane];
        float v3 = g_h32[s3 * 32 + lane];
        a0 = fmaf(w0.x, v0, a0); a1 = fmaf(w0.y, v0, a1);
        a0 = fmaf(w1.x, v1, a0); a1 = fmaf(w1.y, v1, a1);
        a0 = fmaf(w2.x, v2, a0); a1 = fmaf(w2.y, v2, a1);
        a0 = fmaf(w3.x, v3, a0); a1 = fmaf(w3.y, v3, a1);
    }
    for (; k < end; k++) {
        int s = g_src[k];
        float2 w = g_kw[k];
        float v = g_h32[s * 32 + lane];
        a0 = fmaf(w.x, v, a0);
        a1 = fmaf(w.y, v, a1);
    }
    g_h64[node * 64 + lane]      = a0;
    g_h64[node * 64 + 32 + lane] = a1;
}

// ---------------- layer 1 MLP pass A: 64 -> 128, ReLU (SCALAR FFMA) ----------------
// thread per node; h[64] + acc[16] in regs (no spill); W1 rows broadcast from smem;
// hidden written transposed as float2 pairs for coalescing.
__global__ void __launch_bounds__(256) k_mlp1a(
    const float* __restrict__ W1, const float* __restrict__ b1)
{
    __shared__ float W1s[64 * 128];
    __shared__ float b1s[128];
    for (int idx = threadIdx.x; idx < 8192; idx += 256) W1s[idx] = W1[idx];
    if (threadIdx.x < 128) b1s[threadIdx.x] = b1[threadIdx.x];
    __syncthreads();

    int node = blockIdx.x * 256 + threadIdx.x;
    if (node >= N_NODES) return;

    float h[64];
    const float4* hp = (const float4*)&g_h64[node * 64];
#pragma unroll
    for (int j = 0; j < 16; j++) {
        float4 v = hp[j];
        h[4 * j] = v.x; h[4 * j + 1] = v.y; h[4 * j + 2] = v.z; h[4 * j + 3] = v.w;
    }

#pragma unroll 1
    for (int g = 0; g < 8; g++) {          // 8 groups x 16 outputs
        int ob = g * 16;
        float acc[16];
#pragma unroll
        for (int j = 0; j < 16; j++) acc[j] = b1s[ob + j];
#pragma unroll
        for (int i = 0; i < 64; i++) {
            const float4* wr = (const float4*)&W1s[i * 128 + ob];
            float4 wa = wr[0], wb = wr[1], wc = wr[2], wd = wr[3];
            float hv = h[i];
            acc[0]  = fmaf(hv, wa.x, acc[0]);  acc[1]  = fmaf(hv, wa.y, acc[1]);
            acc[2]  = fmaf(hv, wa.z, acc[2]);  acc[3]  = fmaf(hv, wa.w, acc[3]);
            acc[4]  = fmaf(hv, wb.x, acc[4]);  acc[5]  = fmaf(hv, wb.y, acc[5]);
            acc[6]  = fmaf(hv, wb.z, acc[6]);  acc[7]  = fmaf(hv, wb.w, acc[7]);
            acc[8]  = fmaf(hv, wc.x, acc[8]);  acc[9]  = fmaf(hv, wc.y, acc[9]);
            acc[10] = fmaf(hv, wc.z, acc[10]); acc[11] = fmaf(hv, wc.w, acc[11]);
            acc[12] = fmaf(hv, wd.x, acc[12]); acc[13] = fmaf(hv, wd.y, acc[13]);
            acc[14] = fmaf(hv, wd.z, acc[14]); acc[15] = fmaf(hv, wd.w, acc[15]);
        }
#pragma unroll
        for (int j = 0; j < 8; j++) {
            g_hid[(g * 8 + j) * N_NODES + node] =
                make_float2(fmaxf(acc[2 * j], 0.f), fmaxf(acc[2 * j + 1], 0.f));
        }
    }
}

// ---------------- layer 1 MLP pass B: 128 -> 64 + L2 norm (SCALAR FFMA) ----------------
// thread per node; acc[64] in regs (no spill); hidden streamed coalesced in
// chunks of 8 pairs; W2 rows broadcast from smem.
__global__ void __launch_bounds__(256) k_mlp1b(
    const float* __restrict__ W2, const float* __restrict__ b2,
    float* __restrict__ out)
{
    __shared__ float W2s[128 * 64];
    __shared__ float b2s[64];
    for (int idx = threadIdx.x; idx < 8192; idx += 256) W2s[idx] = W2[idx];
    if (threadIdx.x < 64) b2s[threadIdx.x] = b2[threadIdx.x];
    __syncthreads();

    int node = blockIdx.x * 256 + threadIdx.x;
    if (node >= N_NODES) return;

    float acc[64];
#pragma unroll
    for (int m = 0; m < 64; m++) acc[m] = b2s[m];

#pragma unroll 1
    for (int c = 0; c < 8; c++) {          // 8 chunks x 8 hidden-pairs (16 rows)
        float2 hp[8];
#pragma unroll
        for (int q = 0; q < 8; q++) hp[q] = g_hid[(c * 8 + q) * N_NODES + node];
#pragma unroll
        for (int q = 0; q < 8; q++) {
            int r0 = (c * 8 + q) * 2;
            float h0 = hp[q].x;
            const float4* w0 = (const float4*)&W2s[r0 * 64];
#pragma unroll
            for (int j = 0; j < 16; j++) {
                float4 w = w0[j];
                acc[4 * j]     = fmaf(h0, w.x, acc[4 * j]);
                acc[4 * j + 1] = fmaf(h0, w.y, acc[4 * j + 1]);
                acc[4 * j + 2] = fmaf(h0, w.z, acc[4 * j + 2]);
                acc[4 * j + 3] = fmaf(h0, w.w, acc[4 * j + 3]);
            }
            float h1 = hp[q].y;
            const float4* w1 = (const float4*)&W2s[(r0 + 1) * 64];
#pragma unroll
            for (int j = 0; j < 16; j++) {
                float4 w = w1[j];
                acc[4 * j]     = fmaf(h1, w.x, acc[4 * j]);
                acc[4 * j + 1] = fmaf(h1, w.y, acc[4 * j + 1]);
                acc[4 * j + 2] = fmaf(h1, w.z, acc[4 * j + 2]);
                acc[4 * j + 3] = fmaf(h1, w.w, acc[4 * j + 3]);
            }
        }
    }

    float ss = 0.f;
#pragma unroll
    for (int m = 0; m < 64; m++) ss += acc[m] * acc[m];
    float inv = 1.f / fmaxf(sqrtf(ss), 1e-12f);
    float4* op = (float4*)&out[node * 64];
#pragma unroll
    for (int j = 0; j < 16; j++)
        op[j] = make_float4(acc[4 * j] * inv, acc[4 * j + 1] * inv,
                            acc[4 * j + 2] * inv, acc[4 * j + 3] * inv);
}

// ---------------- launch ----------------
extern "C" void kernel_launch(void* const* d_in, const int* in_sizes, int n_in,
                              void* d_out, int out_size) {
    const float* x  = (const float*)d_in[0];
    const int*   ei = (const int*)d_in[1];
    const float* Kw = (const float*)d_in[2];
    const float* W0 = (const float*)d_in[3];
    const float* b0 = (const float*)d_in[4];
    const float* W1 = (const float*)d_in[5];
    const float* b1 = (const float*)d_in[6];
    const float* W2 = (const float*)d_in[7];
    const float* b2 = (const float*)d_in[8];
    float* out = (float*)d_out;

    k_hist<<<12500, 256>>>(ei);           // 1
    k_scan<<<SCAN_BLOCKS, 256>>>();       // 2
    k_scatter<<<12500, 256>>>(ei, Kw);    // 3
    k_conv0<<<25000, 256>>>(x);           // 4  <- ncu capture slot
    k_mlp0<<<782, 256>>>(W0, b0);         // 5
    k_conv1<<<25000, 256>>>();            // 6
    k_mlp1a<<<782, 256>>>(W1, b1);        // 7
    k_mlp1b<<<782, 256>>>(W2, b2, out);   // 8
}

// round 10
// speedup vs baseline: 1.2019x; 1.1925x over previous
#include <cuda_runtime.h>

#define N_NODES 200000
#define N_EDGES 3200000
#define SCAN_BLOCKS 196   // ceil(200000 / 1024)

// ---------------- scratch (device globals; zero-initialized at module load) ----------------
__device__ __align__(16) int    g_deg[N_NODES];      // invariant: zero at kernel_launch entry
__device__ __align__(16) int    g_off[N_NODES + 1];
__device__ __align__(16) int    g_cursor[N_NODES];
__device__ __align__(16) int    g_flag[256];         // invariant: zero at kernel_launch entry
__device__ __align__(16) int    g_src[N_EDGES];
__device__ __align__(16) float2 g_kw[N_EDGES];
__device__ __align__(16) float  g_h16[N_NODES * 16];
__device__ __align__(16) float  g_h32[N_NODES * 32];
__device__ __align__(16) float  g_h64[N_NODES * 64];
__device__ __align__(16) float  g_hid[128 * N_NODES];  // hidden, TRANSPOSED: [channel][node]

// ---------------- tf32 mma helpers ----------------
__device__ __forceinline__ unsigned f2tf32(float x) {
    unsigned u;
    asm("cvt.rna.tf32.f32 %0, %1;" : "=r"(u) : "f"(x));
    return u;
}
__device__ __forceinline__ void split2(float x, unsigned& hi, unsigned& lo) {
    hi = f2tf32(x);
    lo = f2tf32(x - __uint_as_float(hi));
}
// D(16x8) += A(16x8,row) * B(8x8,col); acc in-place
__device__ __forceinline__ void mma8(float* c, const unsigned* a, const unsigned* b) {
    asm("mma.sync.aligned.m16n8k8.row.col.f32.tf32.tf32.f32 "
        "{%0,%1,%2,%3}, {%4,%5,%6,%7}, {%8,%9}, {%0,%1,%2,%3};"
        : "+f"(c[0]), "+f"(c[1]), "+f"(c[2]), "+f"(c[3])
        : "r"(a[0]), "r"(a[1]), "r"(a[2]), "r"(a[3]), "r"(b[0]), "r"(b[1]));
}

// ---------------- CSR build ----------------
__global__ void k_hist(const int* __restrict__ ei) {
    int e = blockIdx.x * blockDim.x + threadIdx.x;
    if (e < N_EDGES) atomicAdd(&g_deg[ei[N_EDGES + e]], 1);
}

// single-pass scan: block-local scan + spin-flag lookback over earlier blocks.
__global__ void k_scan() {
    __shared__ int sh[256];
    __shared__ int red[8];
    int t = threadIdx.x;
    int b = blockIdx.x;
    int base = b * 1024 + t * 4;
    int v0 = 0, v1 = 0, v2 = 0, v3 = 0;
    if (base + 0 < N_NODES) v0 = g_deg[base + 0];
    if (base + 1 < N_NODES) v1 = g_deg[base + 1];
    if (base + 2 < N_NODES) v2 = g_deg[base + 2];
    if (base + 3 < N_NODES) v3 = g_deg[base + 3];
    int tot = v0 + v1 + v2 + v3;
    sh[t] = tot;
    __syncthreads();
    for (int d = 1; d < 256; d <<= 1) {
        int xv = (t >= d) ? sh[t - d] : 0;
        __syncthreads();
        sh[t] += xv;
        __syncthreads();
    }
    if (t == 255) ((volatile int*)g_flag)[b] = sh[255] + 1;  // publish block total

    int v = 0;
    if (t < b) {
        volatile int* f = (volatile int*)g_flag;
        int fv;
        while ((fv = f[t]) == 0) {}
        v = fv - 1;
    }
#pragma unroll
    for (int d = 16; d > 0; d >>= 1) v += __shfl_down_sync(0xffffffffu, v, d);
    if ((t & 31) == 0) red[t >> 5] = v;
    __syncthreads();
    int prefix = red[0] + red[1] + red[2] + red[3] + red[4] + red[5] + red[6] + red[7];

    int excl = sh[t] - tot + prefix;
    int e0 = excl, e1 = excl + v0, e2 = excl + v0 + v1, e3 = excl + v0 + v1 + v2;
    if (base + 0 < N_NODES) { g_off[base + 0] = e0; g_cursor[base + 0] = e0; g_deg[base + 0] = 0; }
    if (base + 1 < N_NODES) { g_off[base + 1] = e1; g_cursor[base + 1] = e1; g_deg[base + 1] = 0; }
    if (base + 2 < N_NODES) { g_off[base + 2] = e2; g_cursor[base + 2] = e2; g_deg[base + 2] = 0; }
    if (base + 3 < N_NODES) { g_off[base + 3] = e3; g_cursor[base + 3] = e3; g_deg[base + 3] = 0; }
    if (b == 0 && t == 0) g_off[N_NODES] = N_EDGES;
}

__global__ void k_scatter(const int* __restrict__ ei, const float* __restrict__ Kw) {
    int e = blockIdx.x * blockDim.x + threadIdx.x;
    if (e < 256) g_flag[e] = 0;   // restore scan-flag invariant for next replay
    if (e >= N_EDGES) return;
    int s = ei[e];
    int d = ei[N_EDGES + e];
    float k0 = Kw[e];
    float k1 = Kw[N_EDGES + e];
    int p = atomicAdd(&g_cursor[d], 1);
    g_src[p] = s;
    g_kw[p] = make_float2(k0, k1);
}

// ---------------- layer 0: conv (d=8, nk=2) ----------------
__global__ void k_conv0(const float* __restrict__ x) {
    int warp = threadIdx.x >> 5, lane = threadIdx.x & 31;
    int node = blockIdx.x * 8 + warp;
    if (node >= N_NODES) return;
    int f = lane & 7, sub = lane >> 3;
    int beg = g_off[node], end = g_off[node + 1];
    float a0 = 0.f, a1 = 0.f;
    for (int k = beg + sub; k < end; k += 4) {
        int s = g_src[k];
        float2 kw = g_kw[k];
        float xv = x[s * 8 + f];
        a0 = fmaf(kw.x, xv, a0);
        a1 = fmaf(kw.y, xv, a1);
    }
    a0 += __shfl_xor_sync(0xffffffffu, a0, 8);
    a0 += __shfl_xor_sync(0xffffffffu, a0, 16);
    a1 += __shfl_xor_sync(0xffffffffu, a1, 8);
    a1 += __shfl_xor_sync(0xffffffffu, a1, 16);
    if (sub == 0) {
        g_h16[node * 16 + f]     = a0;
        g_h16[node * 16 + 8 + f] = a1;
    }
}

// ---------------- layer 0: MLP 16->32 + L2 norm ----------------
__global__ void k_mlp0(const float* __restrict__ W0, const float* __restrict__ b0) {
    __shared__ float W0s[512];
    __shared__ float b0s[32];
    for (int i = threadIdx.x; i < 512; i += blockDim.x) W0s[i] = W0[i];
    if (threadIdx.x < 32) b0s[threadIdx.x] = b0[threadIdx.x];
    __syncthreads();
    int node = blockIdx.x * blockDim.x + threadIdx.x;
    if (node >= N_NODES) return;
    float h[16];
    const float4* hp = (const float4*)&g_h16[node * 16];
#pragma unroll
    for (int j = 0; j < 4; j++) {
        float4 v = hp[j];
        h[4 * j] = v.x; h[4 * j + 1] = v.y; h[4 * j + 2] = v.z; h[4 * j + 3] = v.w;
    }
    float o[32];
    float ss = 0.f;
#pragma unroll
    for (int j = 0; j < 32; j++) {
        float acc = b0s[j];
#pragma unroll
        for (int i = 0; i < 16; i++) acc = fmaf(h[i], W0s[i * 32 + j], acc);
        o[j] = acc;
        ss += acc * acc;
    }
    float inv = 1.f / fmaxf(sqrtf(ss), 1e-12f);
    float4* op = (float4*)&g_h32[node * 32];
#pragma unroll
    for (int j = 0; j < 8; j++)
        op[j] = make_float4(o[4 * j] * inv, o[4 * j + 1] * inv, o[4 * j + 2] * inv, o[4 * j + 3] * inv);
}

// ---------------- layer 1: conv (d=32, nk=2) ----------------
__global__ void k_conv1() {
    int warp = threadIdx.x >> 5, lane = threadIdx.x & 31;
    int node = blockIdx.x * 8 + warp;
    if (node >= N_NODES) return;
    int beg = g_off[node], end = g_off[node + 1];
    float a0 = 0.f, a1 = 0.f;
    int k = beg;
    for (; k + 4 <= end; k += 4) {
        int s0 = g_src[k], s1 = g_src[k + 1], s2 = g_src[k + 2], s3 = g_src[k + 3];
        float2 w0 = g_kw[k], w1 = g_kw[k + 1], w2 = g_kw[k + 2], w3 = g_kw[k + 3];
        float v0 = g_h32[s0 * 32 + lane];
        float v1 = g_h32[s1 * 32 + lane];
        float v2 = g_h32[s2 * 32 + lane];
        float v3 = g_h32[s3 * 32 + lane];
        a0 = fmaf(w0.x, v0, a0); a1 = fmaf(w0.y, v0, a1);
        a0 = fmaf(w1.x, v1, a0); a1 = fmaf(w1.y, v1, a1);
        a0 = fmaf(w2.x, v2, a0); a1 = fmaf(w2.y, v2, a1);
        a0 = fmaf(w3.x, v3, a0); a1 = fmaf(w3.y, v3, a1);
    }
    for (; k < end; k++) {
        int s = g_src[k];
        float2 w = g_kw[k];
        float v = g_h32[s * 32 + lane];
        a0 = fmaf(w.x, v, a0);
        a1 = fmaf(w.y, v, a1);
    }
    g_h64[node * 64 + lane]      = a0;
    g_h64[node * 64 + 32 + lane] = a1;
}

// ---------------- layer 1 MLP pass A: 64 -> 128 + ReLU  (tf32 tensor cores, x3 split) ----
// GEMM computed transposed: D[o][node] = sum_k W1[k][o] * h[node][k] + b1[o].
// Block = 8 warps, 64-node tile. Warp w owns output rows [16w, 16w+16), all 8 node-tiles.
// A-frags from W1 (global, L1-hot), B-frags from padded smem h-tile (conflict-free).
__global__ void __launch_bounds__(256) k_mlp1a(
    const float* __restrict__ W1, const float* __restrict__ b1)
{
    __shared__ float As[64 * 68];   // [node][k], stride 68 -> conflict-free b-frags
    int t = threadIdx.x;
    int w = t >> 5, lane = t & 31;
    int gid = lane >> 2, tig = lane & 3;
    int nbase = blockIdx.x * 64;

    for (int idx = t; idx < 64 * 64; idx += 256) {
        int n = idx >> 6, k = idx & 63;
        As[n * 68 + k] = g_h64[(nbase + n) * 64 + k];
    }
    __syncthreads();

    float acc[8][4];
    float bias0 = b1[16 * w + gid];
    float bias1 = b1[16 * w + gid + 8];
#pragma unroll
    for (int nt = 0; nt < 8; nt++) {
        acc[nt][0] = bias0; acc[nt][1] = bias0;
        acc[nt][2] = bias1; acc[nt][3] = bias1;
    }

#pragma unroll
    for (int ks = 0; ks < 8; ks++) {
        int k0 = ks * 8;
        // A_tile[r][c] = W1[k0+c][16w+r]
        float a0f = W1[(k0 + tig) * 128 + 16 * w + gid];
        float a1f = W1[(k0 + tig) * 128 + 16 * w + gid + 8];
        float a2f = W1[(k0 + tig + 4) * 128 + 16 * w + gid];
        float a3f = W1[(k0 + tig + 4) * 128 + 16 * w + gid + 8];
        unsigned ahi[4], alo[4];
        split2(a0f, ahi[0], alo[0]); split2(a1f, ahi[1], alo[1]);
        split2(a2f, ahi[2], alo[2]); split2(a3f, ahi[3], alo[3]);
#pragma unroll
        for (int nt = 0; nt < 8; nt++) {
            // B_tile[r][c] = h[nbase + nt*8 + c][k0 + r]
            float b0f = As[(nt * 8 + gid) * 68 + k0 + tig];
            float b1f = As[(nt * 8 + gid) * 68 + k0 + tig + 4];
            unsigned bhi[2], blo[2];
            split2(b0f, bhi[0], blo[0]); split2(b1f, bhi[1], blo[1]);
            mma8(acc[nt], alo, bhi);
            mma8(acc[nt], ahi, blo);
            mma8(acc[nt], ahi, bhi);
        }
    }

    // ReLU + store hid[o][node]; paired cols -> float2 (full 32B sectors)
#pragma unroll
    for (int nt = 0; nt < 8; nt++) {
        int node = nbase + nt * 8 + 2 * tig;
        int o0 = 16 * w + gid;
        float2 v0 = make_float2(fmaxf(acc[nt][0], 0.f), fmaxf(acc[nt][1], 0.f));
        float2 v1 = make_float2(fmaxf(acc[nt][2], 0.f), fmaxf(acc[nt][3], 0.f));
        *(float2*)&g_hid[o0 * N_NODES + node]       = v0;
        *(float2*)&g_hid[(o0 + 8) * N_NODES + node] = v1;
    }
}

// ---------------- layer 1 MLP pass B: 128 -> 64 + L2 norm  (tf32 tensor cores) ----------
// D2[m][node] = sum_k W2[k][m] * hid[k][node] + b2[m]; then per-node column L2 norm.
// Block = 8 warps, 64-node tile. Warp w: m-strip (w%4)*16, node-half (w/4)*32 (4 n-tiles).
__global__ void __launch_bounds__(256) k_mlp1b(
    const float* __restrict__ W2, const float* __restrict__ b2,
    float* __restrict__ out)
{
    __shared__ float Hs[128 * 68];  // [k][node], stride 68 -> conflict-free b-frags
    __shared__ float ssb[64];
    __shared__ float invb[64];
    int t = threadIdx.x;
    int w = t >> 5, lane = t & 31;
    int gid = lane >> 2, tig = lane & 3;
    int nbase = blockIdx.x * 64;
    int ms = (w & 3) * 16;      // m-strip base
    int nh = (w >> 2) * 32;     // node-half offset

    for (int idx = t; idx < 128 * 64; idx += 256) {
        int o = idx >> 6, n = idx & 63;
        Hs[o * 68 + n] = g_hid[o * N_NODES + nbase + n];
    }
    if (t < 64) ssb[t] = 0.f;
    __syncthreads();

    float acc[4][4];
    float bias0 = b2[ms + gid];
    float bias1 = b2[ms + gid + 8];
#pragma unroll
    for (int nt = 0; nt < 4; nt++) {
        acc[nt][0] = bias0; acc[nt][1] = bias0;
        acc[nt][2] = bias1; acc[nt][3] = bias1;
    }

#pragma unroll
    for (int ks = 0; ks < 16; ks++) {
        int k0 = ks * 8;
        float a0f = W2[(k0 + tig) * 64 + ms + gid];
        float a1f = W2[(k0 + tig) * 64 + ms + gid + 8];
        float a2f = W2[(k0 + tig + 4) * 64 + ms + gid];
        float a3f = W2[(k0 + tig + 4) * 64 + ms + gid + 8];
        unsigned ahi[4], alo[4];
        split2(a0f, ahi[0], alo[0]); split2(a1f, ahi[1], alo[1]);
        split2(a2f, ahi[2], alo[2]); split2(a3f, ahi[3], alo[3]);
#pragma unroll
        for (int nt = 0; nt < 4; nt++) {
            int ncol = nh + nt * 8 + gid;
            float b0f = Hs[(k0 + tig) * 68 + ncol];
            float b1f = Hs[(k0 + tig + 4) * 68 + ncol];
            unsigned bhi[2], blo[2];
            split2(b0f, bhi[0], blo[0]); split2(b1f, bhi[1], blo[1]);
            mma8(acc[nt], alo, bhi);
            mma8(acc[nt], ahi, blo);
            mma8(acc[nt], ahi, bhi);
        }
    }

    // per-node column sum of squares: reduce over gid (rows in strip), atomic over strips
#pragma unroll
    for (int nt = 0; nt < 4; nt++) {
        float s0 = acc[nt][0] * acc[nt][0] + acc[nt][2] * acc[nt][2];
        float s1 = acc[nt][1] * acc[nt][1] + acc[nt][3] * acc[nt][3];
        s0 += __shfl_xor_sync(0xffffffffu, s0, 4);
        s1 += __shfl_xor_sync(0xffffffffu, s1, 4);
        s0 += __shfl_xor_sync(0xffffffffu, s0, 8);
        s1 += __shfl_xor_sync(0xffffffffu, s1, 8);
        s0 += __shfl_xor_sync(0xffffffffu, s0, 16);
        s1 += __shfl_xor_sync(0xffffffffu, s1, 16);
        if (gid == 0) {
            atomicAdd(&ssb[nh + nt * 8 + 2 * tig], s0);
            atomicAdd(&ssb[nh + nt * 8 + 2 * tig + 1], s1);
        }
    }
    __syncthreads();
    if (t < 64) invb[t] = 1.f / fmaxf(sqrtf(ssb[t]), 1e-12f);
    __syncthreads();

#pragma unroll
    for (int nt = 0; nt < 4; nt++) {
        int col0 = nh + nt * 8 + 2 * tig;
        float i0 = invb[col0], i1 = invb[col0 + 1];
        int node0 = nbase + col0;
        out[node0 * 64 + ms + gid]           = acc[nt][0] * i0;
        out[(node0 + 1) * 64 + ms + gid]     = acc[nt][1] * i1;
        out[node0 * 64 + ms + gid + 8]       = acc[nt][2] * i0;
        out[(node0 + 1) * 64 + ms + gid + 8] = acc[nt][3] * i1;
    }
}

// ---------------- launch ----------------
extern "C" void kernel_launch(void* const* d_in, const int* in_sizes, int n_in,
                              void* d_out, int out_size) {
    const float* x  = (const float*)d_in[0];
    const int*   ei = (const int*)d_in[1];
    const float* Kw = (const float*)d_in[2];
    const float* W0 = (const float*)d_in[3];
    const float* b0 = (const float*)d_in[4];
    const float* W1 = (const float*)d_in[5];
    const float* b1 = (const float*)d_in[6];
    const float* W2 = (const float*)d_in[7];
    const float* b2 = (const float*)d_in[8];
    float* out = (float*)d_out;

    k_hist<<<12500, 256>>>(ei);           // 1
    k_scan<<<SCAN_BLOCKS, 256>>>();       // 2
    k_scatter<<<12500, 256>>>(ei, Kw);    // 3
    k_conv0<<<25000, 256>>>(x);           // 4  <- ncu capture slot
    k_mlp0<<<782, 256>>>(W0, b0);         // 5
    k_conv1<<<25000, 256>>>();            // 6
    k_mlp1a<<<3125, 256>>>(W1, b1);       // 7  (tf32 tensor)
    k_mlp1b<<<3125, 256>>>(W2, b2, out);  // 8  (tf32 tensor)
}

// round 11
// speedup vs baseline: 1.3166x; 1.0955x over previous
#include <cuda_runtime.h>

#define N_NODES 200000
#define N_EDGES 3200000
#define SCAN_BLOCKS 196   // ceil(200000 / 1024)

// ---------------- scratch (device globals; zero-initialized at module load) ----------------
__device__ __align__(16) int    g_deg[N_NODES];      // invariant: zero at kernel_launch entry
__device__ __align__(16) int    g_off[N_NODES + 1];
__device__ __align__(16) int    g_cursor[N_NODES];
__device__ __align__(16) int    g_flag[256];         // invariant: zero at kernel_launch entry
__device__ __align__(16) int    g_src[N_EDGES];
__device__ __align__(16) float2 g_kw[N_EDGES];
__device__ __align__(16) float  g_h16[N_NODES * 16];
__device__ __align__(16) float  g_h32[N_NODES * 32];
__device__ __align__(16) float  g_h64[N_NODES * 64];

// ---------------- tf32 mma helpers ----------------
__device__ __forceinline__ unsigned f2tf32(float x) {
    unsigned u;
    asm("cvt.rna.tf32.f32 %0, %1;" : "=r"(u) : "f"(x));
    return u;
}
__device__ __forceinline__ void split2(float x, unsigned& hi, unsigned& lo) {
    hi = f2tf32(x);
    lo = f2tf32(x - __uint_as_float(hi));
}
// D(16x8) += A(16x8,row) * B(8x8,col); acc in-place
__device__ __forceinline__ void mma8(float* c, const unsigned* a, const unsigned* b) {
    asm("mma.sync.aligned.m16n8k8.row.col.f32.tf32.tf32.f32 "
        "{%0,%1,%2,%3}, {%4,%5,%6,%7}, {%8,%9}, {%0,%1,%2,%3};"
        : "+f"(c[0]), "+f"(c[1]), "+f"(c[2]), "+f"(c[3])
        : "r"(a[0]), "r"(a[1]), "r"(a[2]), "r"(a[3]), "r"(b[0]), "r"(b[1]));
}

// ---------------- CSR build ----------------
__global__ void k_hist(const int* __restrict__ ei) {
    int e = blockIdx.x * blockDim.x + threadIdx.x;
    if (e < N_EDGES) atomicAdd(&g_deg[ei[N_EDGES + e]], 1);
}

// single-pass scan: block-local scan + spin-flag lookback over earlier blocks.
__global__ void k_scan() {
    __shared__ int sh[256];
    __shared__ int red[8];
    int t = threadIdx.x;
    int b = blockIdx.x;
    int base = b * 1024 + t * 4;
    int v0 = 0, v1 = 0, v2 = 0, v3 = 0;
    if (base + 0 < N_NODES) v0 = g_deg[base + 0];
    if (base + 1 < N_NODES) v1 = g_deg[base + 1];
    if (base + 2 < N_NODES) v2 = g_deg[base + 2];
    if (base + 3 < N_NODES) v3 = g_deg[base + 3];
    int tot = v0 + v1 + v2 + v3;
    sh[t] = tot;
    __syncthreads();
    for (int d = 1; d < 256; d <<= 1) {
        int xv = (t >= d) ? sh[t - d] : 0;
        __syncthreads();
        sh[t] += xv;
        __syncthreads();
    }
    if (t == 255) ((volatile int*)g_flag)[b] = sh[255] + 1;  // publish block total

    int v = 0;
    if (t < b) {
        volatile int* f = (volatile int*)g_flag;
        int fv;
        while ((fv = f[t]) == 0) {}
        v = fv - 1;
    }
#pragma unroll
    for (int d = 16; d > 0; d >>= 1) v += __shfl_down_sync(0xffffffffu, v, d);
    if ((t & 31) == 0) red[t >> 5] = v;
    __syncthreads();
    int prefix = red[0] + red[1] + red[2] + red[3] + red[4] + red[5] + red[6] + red[7];

    int excl = sh[t] - tot + prefix;
    int e0 = excl, e1 = excl + v0, e2 = excl + v0 + v1, e3 = excl + v0 + v1 + v2;
    if (base + 0 < N_NODES) { g_off[base + 0] = e0; g_cursor[base + 0] = e0; g_deg[base + 0] = 0; }
    if (base + 1 < N_NODES) { g_off[base + 1] = e1; g_cursor[base + 1] = e1; g_deg[base + 1] = 0; }
    if (base + 2 < N_NODES) { g_off[base + 2] = e2; g_cursor[base + 2] = e2; g_deg[base + 2] = 0; }
    if (base + 3 < N_NODES) { g_off[base + 3] = e3; g_cursor[base + 3] = e3; g_deg[base + 3] = 0; }
    if (b == 0 && t == 0) g_off[N_NODES] = N_EDGES;
}

__global__ void k_scatter(const int* __restrict__ ei, const float* __restrict__ Kw) {
    int e = blockIdx.x * blockDim.x + threadIdx.x;
    if (e < 256) g_flag[e] = 0;   // restore scan-flag invariant for next replay
    if (e >= N_EDGES) return;
    int s = ei[e];
    int d = ei[N_EDGES + e];
    float k0 = Kw[e];
    float k1 = Kw[N_EDGES + e];
    int p = atomicAdd(&g_cursor[d], 1);
    g_src[p] = s;
    g_kw[p] = make_float2(k0, k1);
}

// ---------------- layer 0: conv (d=8, nk=2) ----------------
__global__ void k_conv0(const float* __restrict__ x) {
    int warp = threadIdx.x >> 5, lane = threadIdx.x & 31;
    int node = blockIdx.x * 8 + warp;
    if (node >= N_NODES) return;
    int f = lane & 7, sub = lane >> 3;
    int beg = g_off[node], end = g_off[node + 1];
    float a0 = 0.f, a1 = 0.f;
    for (int k = beg + sub; k < end; k += 4) {
        int s = g_src[k];
        float2 kw = g_kw[k];
        float xv = x[s * 8 + f];
        a0 = fmaf(kw.x, xv, a0);
        a1 = fmaf(kw.y, xv, a1);
    }
    a0 += __shfl_xor_sync(0xffffffffu, a0, 8);
    a0 += __shfl_xor_sync(0xffffffffu, a0, 16);
    a1 += __shfl_xor_sync(0xffffffffu, a1, 8);
    a1 += __shfl_xor_sync(0xffffffffu, a1, 16);
    if (sub == 0) {
        g_h16[node * 16 + f]     = a0;
        g_h16[node * 16 + 8 + f] = a1;
    }
}

// ---------------- layer 0: MLP 16->32 + L2 norm ----------------
__global__ void k_mlp0(const float* __restrict__ W0, const float* __restrict__ b0) {
    __shared__ float W0s[512];
    __shared__ float b0s[32];
    for (int i = threadIdx.x; i < 512; i += blockDim.x) W0s[i] = W0[i];
    if (threadIdx.x < 32) b0s[threadIdx.x] = b0[threadIdx.x];
    __syncthreads();
    int node = blockIdx.x * blockDim.x + threadIdx.x;
    if (node >= N_NODES) return;
    float h[16];
    const float4* hp = (const float4*)&g_h16[node * 16];
#pragma unroll
    for (int j = 0; j < 4; j++) {
        float4 v = hp[j];
        h[4 * j] = v.x; h[4 * j + 1] = v.y; h[4 * j + 2] = v.z; h[4 * j + 3] = v.w;
    }
    float o[32];
    float ss = 0.f;
#pragma unroll
    for (int j = 0; j < 32; j++) {
        float acc = b0s[j];
#pragma unroll
        for (int i = 0; i < 16; i++) acc = fmaf(h[i], W0s[i * 32 + j], acc);
        o[j] = acc;
        ss += acc * acc;
    }
    float inv = 1.f / fmaxf(sqrtf(ss), 1e-12f);
    float4* op = (float4*)&g_h32[node * 32];
#pragma unroll
    for (int j = 0; j < 8; j++)
        op[j] = make_float4(o[4 * j] * inv, o[4 * j + 1] * inv, o[4 * j + 2] * inv, o[4 * j + 3] * inv);
}

// ---------------- layer 1: conv (d=32, nk=2) ----------------
__global__ void k_conv1() {
    int warp = threadIdx.x >> 5, lane = threadIdx.x & 31;
    int node = blockIdx.x * 8 + warp;
    if (node >= N_NODES) return;
    int beg = g_off[node], end = g_off[node + 1];
    float a0 = 0.f, a1 = 0.f;
    int k = beg;
    for (; k + 4 <= end; k += 4) {
        int s0 = g_src[k], s1 = g_src[k + 1], s2 = g_src[k + 2], s3 = g_src[k + 3];
        float2 w0 = g_kw[k], w1 = g_kw[k + 1], w2 = g_kw[k + 2], w3 = g_kw[k + 3];
        float v0 = g_h32[s0 * 32 + lane];
        float v1 = g_h32[s1 * 32 + lane];
        float v2 = g_h32[s2 * 32 + lane];
        float v3 = g_h32[s3 * 32 + lane];
        a0 = fmaf(w0.x, v0, a0); a1 = fmaf(w0.y, v0, a1);
        a0 = fmaf(w1.x, v1, a0); a1 = fmaf(w1.y, v1, a1);
        a0 = fmaf(w2.x, v2, a0); a1 = fmaf(w2.y, v2, a1);
        a0 = fmaf(w3.x, v3, a0); a1 = fmaf(w3.y, v3, a1);
    }
    for (; k < end; k++) {
        int s = g_src[k];
        float2 w = g_kw[k];
        float v = g_h32[s * 32 + lane];
        a0 = fmaf(w.x, v, a0);
        a1 = fmaf(w.y, v, a1);
    }
    g_h64[node * 64 + lane]      = a0;
    g_h64[node * 64 + 32 + lane] = a1;
}

// ---------------- layer 1 MLP FUSED: 64 -> 128 (ReLU) -> 64 + L2 norm (tf32 x3) ----------
// 64-node tile per block, 8 warps. Hidden tile lives only in smem (no g_hid round trip).
// Pass A: warp w -> output rows [16w,16w+16) x all 64 nodes; ReLU -> Hs[o][node].
// Pass B: warp w -> m-strip (w%4)*16, node-half (w/4)*32; per-node column L2 norm.
__global__ void __launch_bounds__(256) k_mlp1f(
    const float* __restrict__ W1, const float* __restrict__ b1,
    const float* __restrict__ W2, const float* __restrict__ b2,
    float* __restrict__ out)
{
    extern __shared__ float smem[];
    float* As  = smem;                    // [64][68]  h tile (stride 68)
    float* Hs  = smem + 64 * 68;          // [128][68] hidden tile (stride 68)
    float* ssb = smem + 64 * 68 + 128 * 68;  // [64]
    float* invb = ssb + 64;               // [64]

    int t = threadIdx.x;
    int w = t >> 5, lane = t & 31;
    int gid = lane >> 2, tig = lane & 3;
    int nbase = blockIdx.x * 64;

    for (int idx = t; idx < 64 * 64; idx += 256) {
        int n = idx >> 6, k = idx & 63;
        As[n * 68 + k] = g_h64[(nbase + n) * 64 + k];
    }
    if (t < 64) ssb[t] = 0.f;
    __syncthreads();

    // ---- pass A: h(64) @ W1(64x128) + b1, ReLU -> Hs ----
    {
        float acc[8][4];
        float bias0 = b1[16 * w + gid];
        float bias1 = b1[16 * w + gid + 8];
#pragma unroll
        for (int nt = 0; nt < 8; nt++) {
            acc[nt][0] = bias0; acc[nt][1] = bias0;
            acc[nt][2] = bias1; acc[nt][3] = bias1;
        }
#pragma unroll
        for (int ks = 0; ks < 8; ks++) {
            int k0 = ks * 8;
            float a0f = W1[(k0 + tig) * 128 + 16 * w + gid];
            float a1f = W1[(k0 + tig) * 128 + 16 * w + gid + 8];
            float a2f = W1[(k0 + tig + 4) * 128 + 16 * w + gid];
            float a3f = W1[(k0 + tig + 4) * 128 + 16 * w + gid + 8];
            unsigned ahi[4], alo[4];
            split2(a0f, ahi[0], alo[0]); split2(a1f, ahi[1], alo[1]);
            split2(a2f, ahi[2], alo[2]); split2(a3f, ahi[3], alo[3]);
#pragma unroll
            for (int nt = 0; nt < 8; nt++) {
                float b0f = As[(nt * 8 + gid) * 68 + k0 + tig];
                float b1f = As[(nt * 8 + gid) * 68 + k0 + tig + 4];
                unsigned bhi[2], blo[2];
                split2(b0f, bhi[0], blo[0]); split2(b1f, bhi[1], blo[1]);
                mma8(acc[nt], alo, bhi);
                mma8(acc[nt], ahi, blo);
                mma8(acc[nt], ahi, bhi);
            }
        }
        // ReLU -> Hs[o][node] (stride 68); pairs are 8B-aligned (even offsets)
        int o0 = 16 * w + gid;
#pragma unroll
        for (int nt = 0; nt < 8; nt++) {
            int n = nt * 8 + 2 * tig;
            *(float2*)&Hs[o0 * 68 + n] =
                make_float2(fmaxf(acc[nt][0], 0.f), fmaxf(acc[nt][1], 0.f));
            *(float2*)&Hs[(o0 + 8) * 68 + n] =
                make_float2(fmaxf(acc[nt][2], 0.f), fmaxf(acc[nt][3], 0.f));
        }
    }
    __syncthreads();

    // ---- pass B: hid(128) @ W2(128x64) + b2 -> L2 norm -> out ----
    int ms = (w & 3) * 16;      // m-strip base
    int nh = (w >> 2) * 32;     // node-half offset
    float acc[4][4];
    {
        float bias0 = b2[ms + gid];
        float bias1 = b2[ms + gid + 8];
#pragma unroll
        for (int nt = 0; nt < 4; nt++) {
            acc[nt][0] = bias0; acc[nt][1] = bias0;
            acc[nt][2] = bias1; acc[nt][3] = bias1;
        }
#pragma unroll
        for (int ks = 0; ks < 16; ks++) {
            int k0 = ks * 8;
            float a0f = W2[(k0 + tig) * 64 + ms + gid];
            float a1f = W2[(k0 + tig) * 64 + ms + gid + 8];
            float a2f = W2[(k0 + tig + 4) * 64 + ms + gid];
            float a3f = W2[(k0 + tig + 4) * 64 + ms + gid + 8];
            unsigned ahi[4], alo[4];
            split2(a0f, ahi[0], alo[0]); split2(a1f, ahi[1], alo[1]);
            split2(a2f, ahi[2], alo[2]); split2(a3f, ahi[3], alo[3]);
#pragma unroll
            for (int nt = 0; nt < 4; nt++) {
                int ncol = nh + nt * 8 + gid;
                float b0f = Hs[(k0 + tig) * 68 + ncol];
                float b1f = Hs[(k0 + tig + 4) * 68 + ncol];
                unsigned bhi[2], blo[2];
                split2(b0f, bhi[0], blo[0]); split2(b1f, bhi[1], blo[1]);
                mma8(acc[nt], alo, bhi);
                mma8(acc[nt], ahi, blo);
                mma8(acc[nt], ahi, bhi);
            }
        }
    }

    // per-node column sum of squares: shuffle-reduce over gid, smem-atomic over m-strips
#pragma unroll
    for (int nt = 0; nt < 4; nt++) {
        float s0 = acc[nt][0] * acc[nt][0] + acc[nt][2] * acc[nt][2];
        float s1 = acc[nt][1] * acc[nt][1] + acc[nt][3] * acc[nt][3];
        s0 += __shfl_xor_sync(0xffffffffu, s0, 4);
        s1 += __shfl_xor_sync(0xffffffffu, s1, 4);
        s0 += __shfl_xor_sync(0xffffffffu, s0, 8);
        s1 += __shfl_xor_sync(0xffffffffu, s1, 8);
        s0 += __shfl_xor_sync(0xffffffffu, s0, 16);
        s1 += __shfl_xor_sync(0xffffffffu, s1, 16);
        if (gid == 0) {
            atomicAdd(&ssb[nh + nt * 8 + 2 * tig], s0);
            atomicAdd(&ssb[nh + nt * 8 + 2 * tig + 1], s1);
        }
    }
    __syncthreads();
    if (t < 64) invb[t] = 1.f / fmaxf(sqrtf(ssb[t]), 1e-12f);
    __syncthreads();

#pragma unroll
    for (int nt = 0; nt < 4; nt++) {
        int col0 = nh + nt * 8 + 2 * tig;
        float i0 = invb[col0], i1 = invb[col0 + 1];
        int node0 = nbase + col0;
        out[node0 * 64 + ms + gid]           = acc[nt][0] * i0;
        out[(node0 + 1) * 64 + ms + gid]     = acc[nt][1] * i1;
        out[node0 * 64 + ms + gid + 8]       = acc[nt][2] * i0;
        out[(node0 + 1) * 64 + ms + gid + 8] = acc[nt][3] * i1;
    }
}

// ---------------- launch ----------------
extern "C" void kernel_launch(void* const* d_in, const int* in_sizes, int n_in,
                              void* d_out, int out_size) {
    const float* x  = (const float*)d_in[0];
    const int*   ei = (const int*)d_in[1];
    const float* Kw = (const float*)d_in[2];
    const float* W0 = (const float*)d_in[3];
    const float* b0 = (const float*)d_in[4];
    const float* W1 = (const float*)d_in[5];
    const float* b1 = (const float*)d_in[6];
    const float* W2 = (const float*)d_in[7];
    const float* b2 = (const float*)d_in[8];
    float* out = (float*)d_out;

    const int mlp1_smem = (64 * 68 + 128 * 68 + 128) * 4;  // 52736 B
    cudaFuncSetAttribute(k_mlp1f, cudaFuncAttributeMaxDynamicSharedMemorySize, mlp1_smem);

    k_hist<<<12500, 256>>>(ei);                         // 1
    k_scan<<<SCAN_BLOCKS, 256>>>();                     // 2
    k_scatter<<<12500, 256>>>(ei, Kw);                  // 3
    k_conv0<<<25000, 256>>>(x);                         // 4  <- ncu capture slot
    k_mlp0<<<782, 256>>>(W0, b0);                       // 5
    k_conv1<<<25000, 256>>>();                          // 6
    k_mlp1f<<<3125, 256, mlp1_smem>>>(W1, b1, W2, b2, out);  // 7
}